// round 12
// baseline (speedup 1.0000x reference)
#include <cuda_runtime.h>
#include <cuda_bf16.h>
#include <cstdint>

typedef unsigned int u32;
typedef unsigned long long u64;

// ---------------- problem constants ----------------
constexpr int BATCH  = 65536;
constexpr int DIN    = 2000;
constexpr int DH1    = 512;
constexpr int DH2    = 256;
constexpr int NP     = 30;
constexpr int NC     = 200;
constexpr int NLAT   = 16;
constexpr int NUM_UM = 2;
constexpr int N_HOT  = 4;
constexpr int N_CH   = 12;
constexpr int N_FH   = 64;
constexpr int N_FEAT = DH2 + NP + N_CH;          // 298
constexpr int NHEAD  = NP + NC + NLAT + NUM_UM;  // 248
constexpr int NHEAD_PAD = 256;
constexpr int K1P = 2048;                        // DIN padded

// ---------------- device scratch ----------------
__device__ __nv_bfloat16 g_a1h[(size_t)BATCH * K1P];
__device__ __nv_bfloat16 g_a1l[(size_t)BATCH * K1P];
__device__ __nv_bfloat16 g_a2h[(size_t)BATCH * DH1];
__device__ __nv_bfloat16 g_a2l[(size_t)BATCH * DH1];
__device__ __nv_bfloat16 g_a3h[(size_t)BATCH * DH2];
__device__ __nv_bfloat16 g_a3l[(size_t)BATCH * DH2];
__device__ __nv_bfloat16 g_b1h[DH1 * K1P], g_b1l[DH1 * K1P];
__device__ __nv_bfloat16 g_b2h[DH2 * DH1], g_b2l[DH2 * DH1];
__device__ __nv_bfloat16 g_b3h[NHEAD_PAD * DH2], g_b3l[NHEAD_PAD * DH2];
__device__ float g_head[(size_t)BATCH * NHEAD_PAD];
__device__ float g_bhead[NHEAD_PAD];

// ---------------- helpers ----------------
__device__ __forceinline__ u32 smem_u32(const void* p) {
    u32 a;
    asm("{ .reg .u64 t; cvta.to.shared.u64 t, %1; cvt.u32.u64 %0, t; }" : "=r"(a) : "l"(p));
    return a;
}
__device__ __forceinline__ u32 sw128(u32 off) { return off ^ ((off >> 3) & 0x70); }

__device__ __forceinline__ void split2(float v, __nv_bfloat16& h, __nv_bfloat16& l) {
    h = __float2bfloat16(v);
    l = __float2bfloat16(v - __bfloat162float(h));
}
__device__ __forceinline__ u32 bf2u(__nv_bfloat16 a, __nv_bfloat16 b) {
    __nv_bfloat162 t; t.x = a; t.y = b;
    return *reinterpret_cast<u32*>(&t);
}

__device__ __forceinline__ void cp16(u32 dst, const void* src) {
    asm volatile("cp.async.cg.shared.global [%0], [%1], 16;" :: "r"(dst), "l"(src));
}
#define CP_COMMIT() asm volatile("cp.async.commit_group;" ::: "memory")
#define CP_WAIT1()  asm volatile("cp.async.wait_group 1;" ::: "memory")

#define LDMX4(r, a) \
    asm volatile("ldmatrix.sync.aligned.m8n8.x4.shared.b16 {%0,%1,%2,%3}, [%4];" \
                 : "=r"((r)[0]), "=r"((r)[1]), "=r"((r)[2]), "=r"((r)[3]) : "r"(a))

__device__ __forceinline__ void mma16816(float* c, const u32* a, const u32* b) {
    asm volatile(
        "mma.sync.aligned.m16n8k16.row.col.f32.bf16.bf16.f32 "
        "{%0,%1,%2,%3}, {%4,%5,%6,%7}, {%8,%9}, {%0,%1,%2,%3};"
        : "+f"(c[0]), "+f"(c[1]), "+f"(c[2]), "+f"(c[3])
        : "r"(a[0]), "r"(a[1]), "r"(a[2]), "r"(a[3]), "r"(b[0]), "r"(b[1]));
}

// ---------------- split-bf16 tensor-core GEMM (mma.sync) ----------------
// CTA 128x128, 256 threads, 8 warps (2M x 4N), warp tile 64x32.
// K staged in 32-chunks; SMEM/stage = 32KB:
//   [A: 128 rows x (Ah 64B | Al 64B)] [B: 128 rows x (Bh 64B | Bl 64B)]
// 3 stages = 96KB -> 2 CTAs/SM (SMEM). Inner loop mf-split in halves so the
// live set (~116 regs) fits the 128-reg cap of __launch_bounds__(256,2) with
// NO spills. Term-major MMA order: 8 independent MMAs between dependent pairs.
// MODE bits: 1 = relu, 2 = write fp32 Cf, 4 = write bf16 split Oh/Ol
template <int MODE>
__global__ __launch_bounds__(256, 2)
void tc_gemm(const __nv_bfloat16* __restrict__ Ah, const __nv_bfloat16* __restrict__ Al,
             const __nv_bfloat16* __restrict__ Bh, const __nv_bfloat16* __restrict__ Bl,
             const float* __restrict__ bias,
             float* __restrict__ Cf,
             __nv_bfloat16* __restrict__ Oh, __nv_bfloat16* __restrict__ Ol,
             int Kp, int N, int T) {
    extern __shared__ char dsm[];
    const u32 db = (smem_u32(dsm) + 1023) & ~1023u;

    const int tid  = threadIdx.x;
    const int lane = tid & 31;
    const int wid  = tid >> 5;
    const int wm   = wid & 1;      // M half
    const int wn   = wid >> 1;     // N quarter
    const int mbase = blockIdx.y * 128;
    const int nbase = blockIdx.x * 128;

    // global load mapping: 2 threads per row; even = hi, odd = lo; 64B each
    const int lrow  = tid >> 1;
    const int lsel  = tid & 1;
    const __nv_bfloat16* pA = (lsel ? Al : Ah) + (size_t)(mbase + lrow) * Kp;
    const __nv_bfloat16* pB = (lsel ? Bl : Bh) + (size_t)(nbase + lrow) * Kp;
    const u32 rb = lrow * 128 + lsel * 64;

    auto issue_loads = [&](int t) {
        const u32 bS = db + (t % 3) * 32768;
        const int ko = t * 32;
#pragma unroll
        for (int i = 0; i < 4; i++) {
            const u32 so = sw128(rb + i * 16);
            cp16(bS + so,         pA + ko + i * 8);
            cp16(bS + 16384 + so, pB + ko + i * 8);
        }
        CP_COMMIT();
    };

    float acc[4][4][4] = {};

    issue_loads(0);
    issue_loads(1);

    // B ldmatrix thread mapping
    const int quad = lane >> 3;
    const int nfo  = quad >> 1;
    const int koff = (quad & 1) * 16;

    for (int t = 0; t < T; t++) {
        CP_WAIT1();
        __syncthreads();
        if (t + 2 < T) issue_loads(t + 2);
        else CP_COMMIT();

        const u32 bA = db + (t % 3) * 32768;
        const u32 bB = bA + 16384;

#pragma unroll
        for (int kk = 0; kk < 2; kk++) {
            // B fragments for this kk (hi + lo), shared across mf halves
            u32 bfh[2][4], bfl[2][4];
#pragma unroll
            for (int g = 0; g < 2; g++) {
                const u32 base = (u32)(wn * 32 + (g * 2 + nfo) * 8 + (lane & 7)) * 128
                                 + kk * 32 + koff;
                LDMX4(bfh[g], bB + sw128(base));
                LDMX4(bfl[g], bB + sw128(base + 64));
            }
            // process mf in two halves to keep A-frag registers small
#pragma unroll
            for (int half = 0; half < 2; half++) {
                u32 afh[2][4], afl[2][4];
#pragma unroll
                for (int m = 0; m < 2; m++) {
                    const int mf = half * 2 + m;
                    const u32 base = (u32)(wm * 64 + mf * 16 + (lane & 15)) * 128
                                     + kk * 32 + ((lane >> 4) << 4);
                    LDMX4(afh[m], bA + sw128(base));
                    LDMX4(afl[m], bA + sw128(base + 64));
                }
                // term-major: 8 independent MMAs between dependent pairs
#pragma unroll
                for (int m = 0; m < 2; m++)
#pragma unroll
                    for (int nf = 0; nf < 4; nf++)
                        mma16816(acc[half * 2 + m][nf], afh[m], bfh[nf >> 1] + 2 * (nf & 1));
#pragma unroll
                for (int m = 0; m < 2; m++)
#pragma unroll
                    for (int nf = 0; nf < 4; nf++)
                        mma16816(acc[half * 2 + m][nf], afl[m], bfh[nf >> 1] + 2 * (nf & 1));
#pragma unroll
                for (int m = 0; m < 2; m++)
#pragma unroll
                    for (int nf = 0; nf < 4; nf++)
                        mma16816(acc[half * 2 + m][nf], afh[m], bfl[nf >> 1] + 2 * (nf & 1));
            }
        }
    }

    // ---------------- epilogue ----------------
#pragma unroll
    for (int nf = 0; nf < 4; nf++) {
        const int colg = nbase + wn * 32 + nf * 8 + ((lane & 3) << 1);
        const float b0 = bias[colg];
        const float b1 = bias[colg + 1];
#pragma unroll
        for (int mf = 0; mf < 4; mf++) {
            const size_t r0 = (size_t)(mbase + wm * 64 + mf * 16 + (lane >> 2));
            const size_t r1 = r0 + 8;
            float v00 = acc[mf][nf][0] + b0;
            float v01 = acc[mf][nf][1] + b1;
            float v10 = acc[mf][nf][2] + b0;
            float v11 = acc[mf][nf][3] + b1;
            if (MODE & 1) {
                v00 = fmaxf(v00, 0.f); v01 = fmaxf(v01, 0.f);
                v10 = fmaxf(v10, 0.f); v11 = fmaxf(v11, 0.f);
            }
            if (MODE & 2) {
                *(float2*)(Cf + r0 * N + colg) = make_float2(v00, v01);
                *(float2*)(Cf + r1 * N + colg) = make_float2(v10, v11);
            }
            if (MODE & 4) {
                __nv_bfloat16 h0, l0, h1, l1;
                split2(v00, h0, l0); split2(v01, h1, l1);
                *(u32*)(Oh + r0 * N + colg) = bf2u(h0, h1);
                *(u32*)(Ol + r0 * N + colg) = bf2u(l0, l1);
                split2(v10, h0, l0); split2(v11, h1, l1);
                *(u32*)(Oh + r1 * N + colg) = bf2u(h0, h1);
                *(u32*)(Ol + r1 * N + colg) = bf2u(l0, l1);
            }
        }
    }
}

// ---------------- conversion kernels ----------------
__global__ void conv_x_kernel(const float* __restrict__ x) {
    const size_t idx = (size_t)blockIdx.x * 256 + threadIdx.x;
    const int row = (int)(idx >> 8);
    const int k0 = (int)(idx & 255) * 8;
    float v[8];
    if (k0 < DIN) {
        const float* p = x + (size_t)row * DIN + k0;
        float4 a = *(const float4*)p;
        float4 b = *(const float4*)(p + 4);
        v[0]=a.x; v[1]=a.y; v[2]=a.z; v[3]=a.w; v[4]=b.x; v[5]=b.y; v[6]=b.z; v[7]=b.w;
    } else {
#pragma unroll
        for (int i = 0; i < 8; i++) v[i] = 0.f;
    }
    u32 hw[4], lw[4];
#pragma unroll
    for (int j = 0; j < 4; j++) {
        __nv_bfloat16 h0, l0, h1, l1;
        split2(v[2*j], h0, l0);
        split2(v[2*j+1], h1, l1);
        hw[j] = bf2u(h0, h1);
        lw[j] = bf2u(l0, l1);
    }
    const size_t off = (size_t)row * K1P + k0;
    *(uint4*)(g_a1h + off) = make_uint4(hw[0], hw[1], hw[2], hw[3]);
    *(uint4*)(g_a1l + off) = make_uint4(lw[0], lw[1], lw[2], lw[3]);
}

// merged weight conversion
constexpr int W1_ELEMS = DH1 * K1P;
constexpr int W2_ELEMS = DH2 * DH1;
constexpr int W3_ELEMS = NHEAD_PAD * DH2;
constexpr int W_TOTAL  = W1_ELEMS + W2_ELEMS + W3_ELEMS;

__global__ void conv_w_kernel(const float* __restrict__ W1, const float* __restrict__ W2,
                              const float* __restrict__ Wp, const float* __restrict__ bp,
                              const float* __restrict__ Wc, const float* __restrict__ bc,
                              const float* __restrict__ Wlat, const float* __restrict__ blat,
                              const float* __restrict__ Wum, const float* __restrict__ bum) {
    int idx = blockIdx.x * 256 + threadIdx.x;
    if (idx < W1_ELEMS) {
        const int n = idx / K1P, k = idx % K1P;
        const float v = (k < DIN) ? W1[(size_t)k * DH1 + n] : 0.f;
        __nv_bfloat16 h, l; split2(v, h, l);
        g_b1h[idx] = h; g_b1l[idx] = l;
        return;
    }
    idx -= W1_ELEMS;
    if (idx < W2_ELEMS) {
        const int n = idx / DH1, k = idx % DH1;
        const float v = W2[(size_t)k * DH2 + n];
        __nv_bfloat16 h, l; split2(v, h, l);
        g_b2h[idx] = h; g_b2l[idx] = l;
        return;
    }
    idx -= W2_ELEMS;
    if (idx < W3_ELEMS) {
        const int c = idx / DH2;
        const int k = idx % DH2;
        float v = 0.f;
        if (c < NP)                       v = Wp[(size_t)k * NP + c];
        else if (c < NP + NC)             v = Wc[(size_t)k * NC + (c - NP)];
        else if (c < NP + NC + NLAT)      v = Wlat[(size_t)k * NLAT + (c - NP - NC)];
        else if (c < NHEAD)               v = Wum[(size_t)k * NUM_UM + (c - NP - NC - NLAT)];
        __nv_bfloat16 h, l; split2(v, h, l);
        g_b3h[idx] = h; g_b3l[idx] = l;
        if (k == 0) {
            float b = 0.f;
            if (c < NP)                   b = bp[c];
            else if (c < NP + NC)         b = bc[c - NP];
            else if (c < NP + NC + NLAT)  b = blat[c - NP - NC];
            else if (c < NHEAD)           b = bum[c - NP - NC - NLAT];
            g_bhead[c] = b;
        }
    }
}

// ---------------- tail ----------------
__global__ void tail_kernel(const float* __restrict__ head,
                            const float* __restrict__ z,
                            const float* __restrict__ cW1, const float* __restrict__ cb1,
                            const float* __restrict__ cW2, const float* __restrict__ cb2,
                            const int* __restrict__ hot, const int* __restrict__ cidx,
                            float* __restrict__ o_parent, float* __restrict__ o_corr,
                            float* __restrict__ o_lat, float* __restrict__ o_um,
                            float* __restrict__ o_mask) {
    const int row = blockIdx.x;
    const int t = threadIdx.x;     // 0..63
    __shared__ float sh[NHEAD];
    __shared__ float sz[DH2];
    __shared__ float sub[N_CH];
    __shared__ float hbuf[N_FH];
    __shared__ int s_pidx;

    const float* hrow = head + (size_t)row * NHEAD_PAD;
    const float* zrow = z + (size_t)row * DH2;
    for (int i = t; i < NHEAD; i += 64) sh[i] = hrow[i];
    for (int i = t; i < DH2; i += 64) sz[i] = zrow[i];
    __syncthreads();

    if (t == 0) {
        int best = 0; float bv = sh[0];
#pragma unroll
        for (int i = 1; i < NP; i++) {
            float v = sh[i];
            if (v > bv) { bv = v; best = i; }
        }
        s_pidx = best;
    }
    __syncthreads();
    const int pidx = s_pidx;

    if (t < NP)     o_parent[(size_t)row * NP + t]   = sh[t];
    if (t < NLAT)   o_lat[(size_t)row * NLAT + t]    = sh[NP + NC + t];
    if (t < NUM_UM) o_um[(size_t)row * NUM_UM + t]   = sh[NP + NC + NLAT + t];

    float active = 0.f;
    for (int n = 0; n < N_HOT; n++) {
        if (hot[n] == pidx) {
            active = 1.f;
            if (t < N_CH) sub[t] = sh[NP + cidx[n * N_CH + t]];
            __syncthreads();
            const float* w1 = cW1 + (size_t)n * N_FEAT * N_FH + t;
            float acc = cb1[n * N_FH + t];
#pragma unroll 4
            for (int f = 0; f < DH2; f++) acc += sz[f] * w1[f * N_FH];
#pragma unroll
            for (int f = 0; f < NP; f++) acc += sh[f] * w1[(DH2 + f) * N_FH];
#pragma unroll
            for (int f = 0; f < N_CH; f++) acc += sub[f] * w1[(DH2 + NP + f) * N_FH];
            hbuf[t] = fmaxf(acc, 0.f);
            __syncthreads();
            if (t < N_CH) {
                const float* w2 = cW2 + (size_t)n * N_FH * N_CH + t;
                float r = cb2[n * N_CH + t];
#pragma unroll
                for (int h = 0; h < N_FH; h++) r += hbuf[h] * w2[h * N_CH];
                sh[NP + cidx[n * N_CH + t]] += r;
            }
            __syncthreads();
        }
    }

    for (int i = t; i < NC; i += 64) o_corr[(size_t)row * NC + i] = sh[NP + i];
    if (t == 0) o_mask[row] = active;
}

// ---------------- launcher ----------------
extern "C" void kernel_launch(void* const* d_in, const int* in_sizes, int n_in,
                              void* d_out, int out_size) {
    const float* x    = (const float*)d_in[0];
    const float* W1   = (const float*)d_in[1];
    const float* b1   = (const float*)d_in[2];
    const float* W2   = (const float*)d_in[3];
    const float* b2   = (const float*)d_in[4];
    const float* Wp   = (const float*)d_in[5];
    const float* bp   = (const float*)d_in[6];
    const float* Wc   = (const float*)d_in[7];
    const float* bc   = (const float*)d_in[8];
    const float* Wlat = (const float*)d_in[9];
    const float* blat = (const float*)d_in[10];
    const float* Wum  = (const float*)d_in[11];
    const float* bum  = (const float*)d_in[12];
    const float* cW1  = (const float*)d_in[13];
    const float* cb1  = (const float*)d_in[14];
    const float* cW2  = (const float*)d_in[15];
    const float* cb2  = (const float*)d_in[16];
    const int*   hot  = (const int*)d_in[17];
    const int*   cidx = (const int*)d_in[18];

    float* out = (float*)d_out;
    float* o_parent = out;
    float* o_corr   = o_parent + (size_t)BATCH * NP;
    float* o_lat    = o_corr   + (size_t)BATCH * NC;
    float* o_um     = o_lat    + (size_t)BATCH * NLAT;
    float* o_z      = o_um     + (size_t)BATCH * NUM_UM;
    float* o_mask   = o_z      + (size_t)BATCH * DH2;

    void *pa1h, *pa1l, *pa2h, *pa2l, *pa3h, *pa3l;
    void *pb1h, *pb1l, *pb2h, *pb2l, *pb3h, *pb3l, *phead, *pbh;
    cudaGetSymbolAddress(&pa1h, g_a1h); cudaGetSymbolAddress(&pa1l, g_a1l);
    cudaGetSymbolAddress(&pa2h, g_a2h); cudaGetSymbolAddress(&pa2l, g_a2l);
    cudaGetSymbolAddress(&pa3h, g_a3h); cudaGetSymbolAddress(&pa3l, g_a3l);
    cudaGetSymbolAddress(&pb1h, g_b1h); cudaGetSymbolAddress(&pb1l, g_b1l);
    cudaGetSymbolAddress(&pb2h, g_b2h); cudaGetSymbolAddress(&pb2l, g_b2l);
    cudaGetSymbolAddress(&pb3h, g_b3h); cudaGetSymbolAddress(&pb3l, g_b3l);
    cudaGetSymbolAddress(&phead, g_head); cudaGetSymbolAddress(&pbh, g_bhead);

    const int SMEMSZ = 3 * 32768 + 1024;
    cudaFuncSetAttribute(tc_gemm<5>, cudaFuncAttributeMaxDynamicSharedMemorySize, SMEMSZ);
    cudaFuncSetAttribute(tc_gemm<7>, cudaFuncAttributeMaxDynamicSharedMemorySize, SMEMSZ);
    cudaFuncSetAttribute(tc_gemm<2>, cudaFuncAttributeMaxDynamicSharedMemorySize, SMEMSZ);

    conv_x_kernel<<<BATCH, 256>>>(x);
    conv_w_kernel<<<(W_TOTAL + 255) / 256, 256>>>(W1, W2, Wp, bp, Wc, bc, Wlat, blat, Wum, bum);

    // GEMM1: relu(x @ W1 + b1) -> split bf16   [65536 x 512], K=2048, T=64
    tc_gemm<5><<<dim3(DH1 / 128, BATCH / 128), 256, SMEMSZ>>>(
        (const __nv_bfloat16*)pa1h, (const __nv_bfloat16*)pa1l,
        (const __nv_bfloat16*)pb1h, (const __nv_bfloat16*)pb1l,
        b1, nullptr, (__nv_bfloat16*)pa2h, (__nv_bfloat16*)pa2l, K1P, DH1, K1P / 32);

    // GEMM2: relu(z1 @ W2 + b2) -> o_z fp32 + split bf16  [65536 x 256], K=512, T=16
    tc_gemm<7><<<dim3(DH2 / 128, BATCH / 128), 256, SMEMSZ>>>(
        (const __nv_bfloat16*)pa2h, (const __nv_bfloat16*)pa2l,
        (const __nv_bfloat16*)pb2h, (const __nv_bfloat16*)pb2l,
        b2, o_z, (__nv_bfloat16*)pa3h, (__nv_bfloat16*)pa3l, DH1, DH2, DH1 / 32);

    // GEMM3: z @ Whead + bhead -> g_head fp32  [65536 x 256], K=256, T=8
    tc_gemm<2><<<dim3(NHEAD_PAD / 128, BATCH / 128), 256, SMEMSZ>>>(
        (const __nv_bfloat16*)pa3h, (const __nv_bfloat16*)pa3l,
        (const __nv_bfloat16*)pb3h, (const __nv_bfloat16*)pb3l,
        (const float*)pbh, (float*)phead, nullptr, nullptr, DH2, NHEAD_PAD, DH2 / 32);

    tail_kernel<<<BATCH, 64>>>((const float*)phead, o_z, cW1, cb1, cW2, cb2, hot, cidx,
                               o_parent, o_corr, o_lat, o_um, o_mask);
}

// round 16
// speedup vs baseline: 1.2424x; 1.2424x over previous
#include <cuda_runtime.h>
#include <cuda_bf16.h>
#include <cstdint>

typedef unsigned int u32;
typedef unsigned long long u64;

// ---------------- problem constants ----------------
constexpr int BATCH  = 65536;
constexpr int DIN    = 2000;
constexpr int DH1    = 512;
constexpr int DH2    = 256;
constexpr int NP     = 30;
constexpr int NC     = 200;
constexpr int NLAT   = 16;
constexpr int NUM_UM = 2;
constexpr int N_HOT  = 4;
constexpr int N_CH   = 12;
constexpr int N_FH   = 64;
constexpr int N_FEAT = DH2 + NP + N_CH;          // 298
constexpr int NHEAD  = NP + NC + NLAT + NUM_UM;  // 248
constexpr int NHEAD_PAD = 256;
constexpr int K1P = 2048;                        // DIN padded

// ---------------- device scratch ----------------
__device__ __nv_bfloat16 g_a2h[(size_t)BATCH * DH1];
__device__ __nv_bfloat16 g_a2l[(size_t)BATCH * DH1];
__device__ __nv_bfloat16 g_a3h[(size_t)BATCH * DH2];
__device__ __nv_bfloat16 g_a3l[(size_t)BATCH * DH2];
__device__ __nv_bfloat16 g_b1h[DH1 * K1P], g_b1l[DH1 * K1P];
__device__ __nv_bfloat16 g_b2h[DH2 * DH1], g_b2l[DH2 * DH1];
__device__ __nv_bfloat16 g_b3h[NHEAD_PAD * DH2], g_b3l[NHEAD_PAD * DH2];
__device__ float g_head[(size_t)BATCH * NHEAD_PAD];
__device__ float g_bhead[NHEAD_PAD];

// ---------------- helpers ----------------
__device__ __forceinline__ u32 smem_u32(const void* p) {
    u32 a;
    asm("{ .reg .u64 t; cvta.to.shared.u64 t, %1; cvt.u32.u64 %0, t; }" : "=r"(a) : "l"(p));
    return a;
}
__device__ __forceinline__ u32 sw128(u32 off) { return off ^ ((off >> 3) & 0x70); }

__device__ __forceinline__ void split2(float v, __nv_bfloat16& h, __nv_bfloat16& l) {
    h = __float2bfloat16(v);
    l = __float2bfloat16(v - __bfloat162float(h));
}
__device__ __forceinline__ u32 bf2u(__nv_bfloat16 a, __nv_bfloat16 b) {
    __nv_bfloat162 t; t.x = a; t.y = b;
    return *reinterpret_cast<u32*>(&t);
}

__device__ __forceinline__ void cp16(u32 dst, const void* src) {
    asm volatile("cp.async.cg.shared.global [%0], [%1], 16;" :: "r"(dst), "l"(src));
}
#define CP_COMMIT() asm volatile("cp.async.commit_group;" ::: "memory")
#define CP_WAIT1()  asm volatile("cp.async.wait_group 1;" ::: "memory")

#define STS128(addr, a, b, c, d) \
    asm volatile("st.shared.v4.b32 [%0], {%1,%2,%3,%4};" \
                 :: "r"(addr), "r"(a), "r"(b), "r"(c), "r"(d) : "memory")

#define LDMX4(r, a) \
    asm volatile("ldmatrix.sync.aligned.m8n8.x4.shared.b16 {%0,%1,%2,%3}, [%4];" \
                 : "=r"((r)[0]), "=r"((r)[1]), "=r"((r)[2]), "=r"((r)[3]) : "r"(a))

__device__ __forceinline__ void mma16816(float* c, const u32* a, const u32* b) {
    asm volatile(
        "mma.sync.aligned.m16n8k16.row.col.f32.bf16.bf16.f32 "
        "{%0,%1,%2,%3}, {%4,%5,%6,%7}, {%8,%9}, {%0,%1,%2,%3};"
        : "+f"(c[0]), "+f"(c[1]), "+f"(c[2]), "+f"(c[3])
        : "r"(a[0]), "r"(a[1]), "r"(a[2]), "r"(a[3]), "r"(b[0]), "r"(b[1]));
}

// ---------------- shared MMA mainloop body (R9-proven) ----------------
// stage layout: [Ah 16K][Al 16K][Bh 16K][Bl 16K] at bA, rows of 128B, sw128
__device__ __forceinline__ void mma_stage(float acc[4][4][4], u32 bA,
                                          int wm, int wn, int lane) {
    const u32 bAlo = bA + 16384;
    const u32 bB   = bA + 32768;
    const u32 bBlo = bA + 49152;
    const int quad = lane >> 3;
    const int nfo  = quad >> 1;
    const int koff = (quad & 1) * 16;

#pragma unroll
    for (int kk = 0; kk < 4; kk++) {
        u32 afh[4][4], afl[4][4];
#pragma unroll
        for (int mf = 0; mf < 4; mf++) {
            const u32 base = (u32)(wm * 64 + mf * 16 + (lane & 15)) * 128
                             + kk * 32 + ((lane >> 4) << 4);
            LDMX4(afh[mf], bA + sw128(base));
            LDMX4(afl[mf], bAlo + sw128(base));
        }
        u32 bfh[2][4], bfl[2][4];
#pragma unroll
        for (int g = 0; g < 2; g++) {
            const u32 base = (u32)(wn * 32 + (g * 2 + nfo) * 8 + (lane & 7)) * 128
                             + kk * 32 + koff;
            LDMX4(bfh[g], bB + sw128(base));
            LDMX4(bfl[g], bBlo + sw128(base));
        }
        // term-major: 16 independent MMAs between dependent pairs
#pragma unroll
        for (int mf = 0; mf < 4; mf++)
#pragma unroll
            for (int nf = 0; nf < 4; nf++)
                mma16816(acc[mf][nf], afh[mf], bfh[nf >> 1] + 2 * (nf & 1));
#pragma unroll
        for (int mf = 0; mf < 4; mf++)
#pragma unroll
            for (int nf = 0; nf < 4; nf++)
                mma16816(acc[mf][nf], afl[mf], bfh[nf >> 1] + 2 * (nf & 1));
#pragma unroll
        for (int mf = 0; mf < 4; mf++)
#pragma unroll
            for (int nf = 0; nf < 4; nf++)
                mma16816(acc[mf][nf], afh[mf], bfl[nf >> 1] + 2 * (nf & 1));
    }
}

// shared epilogue. MODE bits: 1=relu, 2=write fp32 Cf, 4=write bf16 split Oh/Ol
template <int MODE>
__device__ __forceinline__ void epilogue(float acc[4][4][4],
                                         const float* __restrict__ bias,
                                         float* __restrict__ Cf,
                                         __nv_bfloat16* __restrict__ Oh,
                                         __nv_bfloat16* __restrict__ Ol,
                                         int N, int mbase, int nbase,
                                         int wm, int wn, int lane) {
#pragma unroll
    for (int nf = 0; nf < 4; nf++) {
        const int colg = nbase + wn * 32 + nf * 8 + ((lane & 3) << 1);
        const float b0 = bias[colg];
        const float b1 = bias[colg + 1];
#pragma unroll
        for (int mf = 0; mf < 4; mf++) {
            const size_t r0 = (size_t)(mbase + wm * 64 + mf * 16 + (lane >> 2));
            const size_t r1 = r0 + 8;
            float v00 = acc[mf][nf][0] + b0;
            float v01 = acc[mf][nf][1] + b1;
            float v10 = acc[mf][nf][2] + b0;
            float v11 = acc[mf][nf][3] + b1;
            if (MODE & 1) {
                v00 = fmaxf(v00, 0.f); v01 = fmaxf(v01, 0.f);
                v10 = fmaxf(v10, 0.f); v11 = fmaxf(v11, 0.f);
            }
            if (MODE & 2) {
                *(float2*)(Cf + r0 * N + colg) = make_float2(v00, v01);
                *(float2*)(Cf + r1 * N + colg) = make_float2(v10, v11);
            }
            if (MODE & 4) {
                __nv_bfloat16 h0, l0, h1, l1;
                split2(v00, h0, l0); split2(v01, h1, l1);
                *(u32*)(Oh + r0 * N + colg) = bf2u(h0, h1);
                *(u32*)(Ol + r0 * N + colg) = bf2u(l0, l1);
                split2(v10, h0, l0); split2(v11, h1, l1);
                *(u32*)(Oh + r1 * N + colg) = bf2u(h0, h1);
                *(u32*)(Ol + r1 * N + colg) = bf2u(l0, l1);
            }
        }
    }
}

// ---------------- generic split-bf16 GEMM (R9 core: occ-1, 64KB stages) ----------------
template <int MODE>
__global__ __launch_bounds__(256, 1)
void tc_gemm(const __nv_bfloat16* __restrict__ Ah, const __nv_bfloat16* __restrict__ Al,
             const __nv_bfloat16* __restrict__ Bh, const __nv_bfloat16* __restrict__ Bl,
             const float* __restrict__ bias,
             float* __restrict__ Cf,
             __nv_bfloat16* __restrict__ Oh, __nv_bfloat16* __restrict__ Ol,
             int Kp, int N, int T) {
    extern __shared__ char dsm[];
    const u32 db = (smem_u32(dsm) + 1023) & ~1023u;

    const int tid  = threadIdx.x;
    const int lane = tid & 31;
    const int wid  = tid >> 5;
    const int wm   = wid & 1;
    const int wn   = wid >> 1;
    const int mbase = blockIdx.y * 128;
    const int nbase = blockIdx.x * 128;

    const int lrow  = tid >> 1;
    const int lhalf = tid & 1;
    const __nv_bfloat16* pAh = Ah + (size_t)(mbase + lrow) * Kp + lhalf * 32;
    const __nv_bfloat16* pAl = Al + (size_t)(mbase + lrow) * Kp + lhalf * 32;
    const __nv_bfloat16* pBh = Bh + (size_t)(nbase + lrow) * Kp + lhalf * 32;
    const __nv_bfloat16* pBl = Bl + (size_t)(nbase + lrow) * Kp + lhalf * 32;
    const u32 rb = lrow * 128 + lhalf * 64;

    auto issue_loads = [&](int t) {
        const u32 bS = db + (t % 3) * 65536;
        const int ko = t * 64;
#pragma unroll
        for (int i = 0; i < 4; i++) {
            const u32 so = sw128(rb + i * 16);
            cp16(bS + so,         pAh + ko + i * 8);
            cp16(bS + 16384 + so, pAl + ko + i * 8);
            cp16(bS + 32768 + so, pBh + ko + i * 8);
            cp16(bS + 49152 + so, pBl + ko + i * 8);
        }
        CP_COMMIT();
    };

    float acc[4][4][4] = {};

    issue_loads(0);
    issue_loads(1);

    for (int t = 0; t < T; t++) {
        CP_WAIT1();
        __syncthreads();
        if (t + 2 < T) issue_loads(t + 2);
        else CP_COMMIT();
        mma_stage(acc, db + (t % 3) * 65536, wm, wn, lane);
    }

    epilogue<MODE>(acc, bias, Cf, Oh, Ol, N, mbase, nbase, wm, wn, lane);
}

// ---------------- GEMM1 with fused x-split (A: fp32 LDG -> split -> STS) ----------------
// A stage tile 128x64 fp32: 2 threads/row, 32 floats each. B via cp.async (hi+lo).
// Loop order (race-free): CP_WAIT1 -> STS A(t) -> __syncthreads -> issue_B(t+2)
// -> load_x(t+1) -> mma_stage(t). issue_B after the barrier so stage (t-1)%3's
// B is not overwritten while laggard warps still read it (matches R9 schedule).
__global__ __launch_bounds__(256, 1)
void tc_gemm1(const float* __restrict__ x,
              const __nv_bfloat16* __restrict__ Bh, const __nv_bfloat16* __restrict__ Bl,
              const float* __restrict__ bias,
              __nv_bfloat16* __restrict__ Oh, __nv_bfloat16* __restrict__ Ol) {
    constexpr int T = K1P / 64;   // 32
    extern __shared__ char dsm[];
    const u32 db = (smem_u32(dsm) + 1023) & ~1023u;

    const int tid  = threadIdx.x;
    const int lane = tid & 31;
    const int wid  = tid >> 5;
    const int wm   = wid & 1;
    const int wn   = wid >> 1;
    const int mbase = blockIdx.y * 128;
    const int nbase = blockIdx.x * 128;

    const int lrow  = tid >> 1;
    const int lhalf = tid & 1;
    const float* px = x + (size_t)(mbase + lrow) * DIN;
    const __nv_bfloat16* pBh = Bh + (size_t)(nbase + lrow) * K1P + lhalf * 32;
    const __nv_bfloat16* pBl = Bl + (size_t)(nbase + lrow) * K1P + lhalf * 32;
    const u32 rb = lrow * 128 + lhalf * 64;

    auto issue_B = [&](int t) {
        const u32 bS = db + (t % 3) * 65536;
        const int ko = t * 64;
#pragma unroll
        for (int i = 0; i < 4; i++) {
            const u32 so = sw128(rb + i * 16);
            cp16(bS + 32768 + so, pBh + ko + i * 8);
            cp16(bS + 49152 + so, pBl + ko + i * 8);
        }
        CP_COMMIT();
    };

    float4 cur[8];
    auto load_x = [&](int t) {
        const int kbase = t * 64 + lhalf * 32;
#pragma unroll
        for (int i = 0; i < 8; i++) {
            const int k = kbase + i * 4;
            cur[i] = (k < DIN) ? *(const float4*)(px + k)
                               : make_float4(0.f, 0.f, 0.f, 0.f);
        }
    };

    float acc[4][4][4] = {};

    issue_B(0);
    issue_B(1);
    load_x(0);

    for (int t = 0; t < T; t++) {
        CP_WAIT1();                // B stage t resident (this thread's copies)
        // STS split-A for stage t. Last reader of this A buffer was
        // mma_stage(t-3), fenced by the barriers of iterations t-2 and t-1.
        {
            const u32 bS = db + (t % 3) * 65536;
            u32 hw[16], lw[16];
#pragma unroll
            for (int j = 0; j < 8; j++) {
                __nv_bfloat16 h0, l0, h1, l1, h2, l2, h3, l3;
                split2(cur[j].x, h0, l0); split2(cur[j].y, h1, l1);
                split2(cur[j].z, h2, l2); split2(cur[j].w, h3, l3);
                hw[2 * j]     = bf2u(h0, h1);
                hw[2 * j + 1] = bf2u(h2, h3);
                lw[2 * j]     = bf2u(l0, l1);
                lw[2 * j + 1] = bf2u(l2, l3);
            }
#pragma unroll
            for (int i = 0; i < 4; i++) {
                const u32 so = sw128(rb + i * 16);
                STS128(bS + so,         hw[4*i], hw[4*i+1], hw[4*i+2], hw[4*i+3]);
                STS128(bS + 16384 + so, lw[4*i], lw[4*i+1], lw[4*i+2], lw[4*i+3]);
            }
        }
        __syncthreads();                    // A STS visible + all warps done with mma(t-1)
        if (t + 2 < T) issue_B(t + 2);      // safe: barrier-ordered after mma(t-1)
        else CP_COMMIT();
        if (t + 1 < T) load_x(t + 1);       // LDG hidden under MMA below
        mma_stage(acc, db + (t % 3) * 65536, wm, wn, lane);
    }

    epilogue<5>(acc, bias, nullptr, Oh, Ol, DH1, mbase, nbase, wm, wn, lane);
}

// ---------------- merged weight conversion ----------------
constexpr int W1_ELEMS = DH1 * K1P;
constexpr int W2_ELEMS = DH2 * DH1;
constexpr int W3_ELEMS = NHEAD_PAD * DH2;
constexpr int W_TOTAL  = W1_ELEMS + W2_ELEMS + W3_ELEMS;

__global__ void conv_w_kernel(const float* __restrict__ W1, const float* __restrict__ W2,
                              const float* __restrict__ Wp, const float* __restrict__ bp,
                              const float* __restrict__ Wc, const float* __restrict__ bc,
                              const float* __restrict__ Wlat, const float* __restrict__ blat,
                              const float* __restrict__ Wum, const float* __restrict__ bum) {
    int idx = blockIdx.x * 256 + threadIdx.x;
    if (idx < W1_ELEMS) {
        const int n = idx / K1P, k = idx % K1P;
        const float v = (k < DIN) ? W1[(size_t)k * DH1 + n] : 0.f;
        __nv_bfloat16 h, l; split2(v, h, l);
        g_b1h[idx] = h; g_b1l[idx] = l;
        return;
    }
    idx -= W1_ELEMS;
    if (idx < W2_ELEMS) {
        const int n = idx / DH1, k = idx % DH1;
        const float v = W2[(size_t)k * DH2 + n];
        __nv_bfloat16 h, l; split2(v, h, l);
        g_b2h[idx] = h; g_b2l[idx] = l;
        return;
    }
    idx -= W2_ELEMS;
    if (idx < W3_ELEMS) {
        const int c = idx / DH2;
        const int k = idx % DH2;
        float v = 0.f;
        if (c < NP)                       v = Wp[(size_t)k * NP + c];
        else if (c < NP + NC)             v = Wc[(size_t)k * NC + (c - NP)];
        else if (c < NP + NC + NLAT)      v = Wlat[(size_t)k * NLAT + (c - NP - NC)];
        else if (c < NHEAD)               v = Wum[(size_t)k * NUM_UM + (c - NP - NC - NLAT)];
        __nv_bfloat16 h, l; split2(v, h, l);
        g_b3h[idx] = h; g_b3l[idx] = l;
        if (k == 0) {
            float b = 0.f;
            if (c < NP)                   b = bp[c];
            else if (c < NP + NC)         b = bc[c - NP];
            else if (c < NP + NC + NLAT)  b = blat[c - NP - NC];
            else if (c < NHEAD)           b = bum[c - NP - NC - NLAT];
            g_bhead[c] = b;
        }
    }
}

// ---------------- tail ----------------
__global__ void tail_kernel(const float* __restrict__ head,
                            const float* __restrict__ z,
                            const float* __restrict__ cW1, const float* __restrict__ cb1,
                            const float* __restrict__ cW2, const float* __restrict__ cb2,
                            const int* __restrict__ hot, const int* __restrict__ cidx,
                            float* __restrict__ o_parent, float* __restrict__ o_corr,
                            float* __restrict__ o_lat, float* __restrict__ o_um,
                            float* __restrict__ o_mask) {
    const int row = blockIdx.x;
    const int t = threadIdx.x;     // 0..63
    __shared__ float sh[NHEAD];
    __shared__ float sz[DH2];
    __shared__ float sub[N_CH];
    __shared__ float hbuf[N_FH];
    __shared__ int s_pidx;

    const float* hrow = head + (size_t)row * NHEAD_PAD;
    const float* zrow = z + (size_t)row * DH2;
    for (int i = t; i < NHEAD; i += 64) sh[i] = hrow[i];
    for (int i = t; i < DH2; i += 64) sz[i] = zrow[i];
    __syncthreads();

    if (t == 0) {
        int best = 0; float bv = sh[0];
#pragma unroll
        for (int i = 1; i < NP; i++) {
            float v = sh[i];
            if (v > bv) { bv = v; best = i; }
        }
        s_pidx = best;
    }
    __syncthreads();
    const int pidx = s_pidx;

    if (t < NP)     o_parent[(size_t)row * NP + t]   = sh[t];
    if (t < NLAT)   o_lat[(size_t)row * NLAT + t]    = sh[NP + NC + t];
    if (t < NUM_UM) o_um[(size_t)row * NUM_UM + t]   = sh[NP + NC + NLAT + t];

    float active = 0.f;
    for (int n = 0; n < N_HOT; n++) {
        if (hot[n] == pidx) {
            active = 1.f;
            if (t < N_CH) sub[t] = sh[NP + cidx[n * N_CH + t]];
            __syncthreads();
            const float* w1 = cW1 + (size_t)n * N_FEAT * N_FH + t;
            float acc = cb1[n * N_FH + t];
#pragma unroll 4
            for (int f = 0; f < DH2; f++) acc += sz[f] * w1[f * N_FH];
#pragma unroll
            for (int f = 0; f < NP; f++) acc += sh[f] * w1[(DH2 + f) * N_FH];
#pragma unroll
            for (int f = 0; f < N_CH; f++) acc += sub[f] * w1[(DH2 + NP + f) * N_FH];
            hbuf[t] = fmaxf(acc, 0.f);
            __syncthreads();
            if (t < N_CH) {
                const float* w2 = cW2 + (size_t)n * N_FH * N_CH + t;
                float r = cb2[n * N_CH + t];
#pragma unroll
                for (int h = 0; h < N_FH; h++) r += hbuf[h] * w2[h * N_CH];
                sh[NP + cidx[n * N_CH + t]] += r;
            }
            __syncthreads();
        }
    }

    for (int i = t; i < NC; i += 64) o_corr[(size_t)row * NC + i] = sh[NP + i];
    if (t == 0) o_mask[row] = active;
}

// ---------------- launcher ----------------
extern "C" void kernel_launch(void* const* d_in, const int* in_sizes, int n_in,
                              void* d_out, int out_size) {
    const float* x    = (const float*)d_in[0];
    const float* W1   = (const float*)d_in[1];
    const float* b1   = (const float*)d_in[2];
    const float* W2   = (const float*)d_in[3];
    const float* b2   = (const float*)d_in[4];
    const float* Wp   = (const float*)d_in[5];
    const float* bp   = (const float*)d_in[6];
    const float* Wc   = (const float*)d_in[7];
    const float* bc   = (const float*)d_in[8];
    const float* Wlat = (const float*)d_in[9];
    const float* blat = (const float*)d_in[10];
    const float* Wum  = (const float*)d_in[11];
    const float* bum  = (const float*)d_in[12];
    const float* cW1  = (const float*)d_in[13];
    const float* cb1  = (const float*)d_in[14];
    const float* cW2  = (const float*)d_in[15];
    const float* cb2  = (const float*)d_in[16];
    const int*   hot  = (const int*)d_in[17];
    const int*   cidx = (const int*)d_in[18];

    float* out = (float*)d_out;
    float* o_parent = out;
    float* o_corr   = o_parent + (size_t)BATCH * NP;
    float* o_lat    = o_corr   + (size_t)BATCH * NC;
    float* o_um     = o_lat    + (size_t)BATCH * NLAT;
    float* o_z      = o_um     + (size_t)BATCH * NUM_UM;
    float* o_mask   = o_z      + (size_t)BATCH * DH2;

    void *pa2h, *pa2l, *pa3h, *pa3l;
    void *pb1h, *pb1l, *pb2h, *pb2l, *pb3h, *pb3l, *phead, *pbh;
    cudaGetSymbolAddress(&pa2h, g_a2h); cudaGetSymbolAddress(&pa2l, g_a2l);
    cudaGetSymbolAddress(&pa3h, g_a3h); cudaGetSymbolAddress(&pa3l, g_a3l);
    cudaGetSymbolAddress(&pb1h, g_b1h); cudaGetSymbolAddress(&pb1l, g_b1l);
    cudaGetSymbolAddress(&pb2h, g_b2h); cudaGetSymbolAddress(&pb2l, g_b2l);
    cudaGetSymbolAddress(&pb3h, g_b3h); cudaGetSymbolAddress(&pb3l, g_b3l);
    cudaGetSymbolAddress(&phead, g_head); cudaGetSymbolAddress(&pbh, g_bhead);

    const int SMEMSZ = 3 * 65536 + 1024;
    cudaFuncSetAttribute(tc_gemm1,   cudaFuncAttributeMaxDynamicSharedMemorySize, SMEMSZ);
    cudaFuncSetAttribute(tc_gemm<7>, cudaFuncAttributeMaxDynamicSharedMemorySize, SMEMSZ);
    cudaFuncSetAttribute(tc_gemm<2>, cudaFuncAttributeMaxDynamicSharedMemorySize, SMEMSZ);

    conv_w_kernel<<<(W_TOTAL + 255) / 256, 256>>>(W1, W2, Wp, bp, Wc, bc, Wlat, blat, Wum, bum);

    // GEMM1 (fused x-split): relu(x @ W1 + b1) -> split bf16  [65536 x 512], K=2048
    tc_gemm1<<<dim3(DH1 / 128, BATCH / 128), 256, SMEMSZ>>>(
        x, (const __nv_bfloat16*)pb1h, (const __nv_bfloat16*)pb1l,
        b1, (__nv_bfloat16*)pa2h, (__nv_bfloat16*)pa2l);

    // GEMM2: relu(z1 @ W2 + b2) -> o_z fp32 + split bf16  [65536 x 256], K=512, T=8
    tc_gemm<7><<<dim3(DH2 / 128, BATCH / 128), 256, SMEMSZ>>>(
        (const __nv_bfloat16*)pa2h, (const __nv_bfloat16*)pa2l,
        (const __nv_bfloat16*)pb2h, (const __nv_bfloat16*)pb2l,
        b2, o_z, (__nv_bfloat16*)pa3h, (__nv_bfloat16*)pa3l, DH1, DH2, DH1 / 64);

    // GEMM3: z @ Whead + bhead -> g_head fp32  [65536 x 256], K=256, T=4
    tc_gemm<2><<<dim3(NHEAD_PAD / 128, BATCH / 128), 256, SMEMSZ>>>(
        (const __nv_bfloat16*)pa3h, (const __nv_bfloat16*)pa3l,
        (const __nv_bfloat16*)pb3h, (const __nv_bfloat16*)pb3l,
        (const float*)pbh, (float*)phead, nullptr, nullptr, DH2, NHEAD_PAD, DH2 / 64);

    tail_kernel<<<BATCH, 64>>>((const float*)phead, o_z, cW1, cb1, cW2, cb2, hot, cidx,
                               o_parent, o_corr, o_lat, o_um, o_mask);
}